// round 17
// baseline (speedup 1.0000x reference)
#include <cuda_runtime.h>
#include <cuda_fp16.h>
#include <cstdint>

#define CIN   3
#define HH    64
#define WW    64
#define HC    128
#define NCTA  128
#define NTHR  1024
#define CLU   4
#define ASTE  144                 // A row stride (fp16 elems) = 288 B
#define BSTE  272                 // B row stride (fp16 elems) = 544 B

// smem byte offsets
#define WI_OFF 0                  // 7*128 floats = 3584 B
#define A0_OFF 3584               // 65 x 288 B = 18720 B
#define A1_OFF 22304
#define B_OFF  41024              // 128 x 544 B = 69632 B
#define SMEM_BYTES 110656

typedef __half fp16;

__device__ __forceinline__ unsigned smem_u32(const void* p) {
    unsigned a;
    asm("{ .reg .u64 t; cvta.to.shared.u64 t, %1; cvt.u32.u64 %0, t; }" : "=r"(a) : "l"(p));
    return a;
}
__device__ __forceinline__ float sigm(float v) { return 1.f / (1.f + __expf(-v)); }
// quad permutation within each 16-block: (2c,2c+1,2c+8,2c+9) stored contiguously
__device__ __forceinline__ int kperm16(int k) {
    int kk = k & 15;
    return (k & ~15) + (((kk & 7) >> 1) << 2) + (kk & 1) + (((kk >> 3) & 1) << 1);
}

#define MMA16(c0_,c1_,c2_,c3_,a0_,a1_,a2_,a3_,b0_,b1_) \
    asm volatile("mma.sync.aligned.m16n8k16.row.col.f32.f16.f16.f32 " \
        "{%0,%1,%2,%3}, {%4,%5,%6,%7}, {%8,%9}, {%0,%1,%2,%3};" \
        : "+f"(c0_), "+f"(c1_), "+f"(c2_), "+f"(c3_) \
        : "r"(a0_), "r"(a1_), "r"(a2_), "r"(a3_), "r"(b0_), "r"(b1_))

__global__ __launch_bounds__(NTHR, 1) __cluster_dims__(CLU, 1, 1)
void rowlstm_kernel(const float* __restrict__ x,
                    const float* __restrict__ W_is,
                    const float* __restrict__ b_is,
                    const float* __restrict__ W_ss,
                    const float* __restrict__ b_ss,
                    const float* __restrict__ h0,
                    const float* __restrict__ c0,
                    float* __restrict__ out)
{
    extern __shared__ char smc[];
    float* WIs = (float*)(smc + WI_OFF);
    fp16*  Bsm = (fp16*)(smc + B_OFF);

    const int tid = threadIdx.x, wid = tid >> 5, lane = tid & 31;
    const int b = blockIdx.x >> 2;
    unsigned rank; asm("mov.u32 %0, %%cluster_ctarank;" : "=r"(rank));
    const int t = (int)rank;
    const unsigned sb = smem_u32(smc);

    // ---- one-time fills ----
    // B[n][k]: k = tap*128 + kperm16(ci); n -> (gate, cil): g = bit0+2*bit3,
    // cil = bits[1:2] + 4*bit4 + 8*bits[5:6]
    for (int idx = tid; idx < HC * 256; idx += NTHR) {
        int n = idx >> 8, k = idx & 255;
        int tap = k >> 7, ci = k & 127;
        int g   = (n & 1) | (((n >> 3) & 1) << 1);
        int cil = ((n >> 1) & 3) | (((n >> 4) & 1) << 2) | (((n >> 5) & 3) << 3);
        int co  = g * HC + t * 32 + cil;
        Bsm[n * BSTE + tap * 128 + kperm16(ci)] = __float2half(W_ss[(co * HC + ci) * 3 + tap]);
    }
    for (int idx = tid; idx < 7 * 128; idx += NTHR) {
        int row = idx >> 7, n = idx & 127;
        int g   = (n & 1) | (((n >> 3) & 1) << 1);
        int cil = ((n >> 1) & 3) | (((n >> 4) & 1) << 2) | (((n >> 5) & 3) << 3);
        int co  = g * HC + t * 32 + cil;
        float v;
        if (row < 6) { int tap = row / 3, cn = row - tap * 3; v = W_is[(co * CIN + cn) * 3 + tap]; }
        else v = b_is[co] + b_ss[co];
        WIs[row * 128 + n] = v;
    }
    // A buffers: fp16 h[w] at row w+1, permuted cols; row 0 = zeros (both buffers)
    for (int idx = tid; idx < 64 * 128; idx += NTHR) {
        int w = idx >> 7, ci = idx & 127;
        ((fp16*)(smc + A0_OFF))[(w + 1) * ASTE + kperm16(ci)] = __float2half(h0[ci * WW + w]);
    }
    for (int idx = tid; idx < ASTE; idx += NTHR) {
        ((fp16*)(smc + A0_OFF))[idx] = __float2half(0.f);
        ((fp16*)(smc + A1_OFF))[idx] = __float2half(0.f);
    }
    __syncthreads();

    // 32 warps: warp tile M=16 (warp_m 0..3), N=16 (warp_n 0..7)
    const int warp_m = wid >> 3, warp_n = wid & 7;
    const int m0 = warp_m * 16, n0 = warp_n * 16;
    const int r4 = lane >> 2, c4 = lane & 3;

    // thread's single hidden channel (ci-local): c4 + 4*(warp_n&1) + 8*(warp_n>>1)
    const int cig  = t * 32 + c4 + 4 * (warp_n & 1) + 8 * (warp_n >> 1);
    const int spos = kperm16(cig - t * 32) + t * 32;

    float creg[2];
    #pragma unroll
    for (int rs = 0; rs < 2; rs++)
        creg[rs] = c0[cig * WW + (m0 + rs * 8 + r4)];

    unsigned peer[CLU];
    #pragma unroll
    for (int r = 0; r < CLU; r++)
        asm("mapa.shared::cluster.u32 %0, %1, %2;" : "=r"(peer[r]) : "r"(sb), "r"(r));

    // prologue cluster sync
    asm volatile("barrier.cluster.arrive.aligned;" ::: "memory");
    asm volatile("barrier.cluster.wait.aligned;" ::: "memory");

    for (int s = 0; s < HH; s++) {
        const fp16*    Ac  = (const fp16*)(smc + ((s & 1) ? A1_OFF : A0_OFF));
        fp16*          An  = (fp16*)      (smc + ((s & 1) ? A0_OFF : A1_OFF));
        const unsigned AnB = (unsigned)((s & 1) ? A0_OFF : A1_OFF);

        // ---- acc init = bias + x-projection (fp32 exact) ----
        float xv[2][6];
        #pragma unroll
        for (int rs = 0; rs < 2; rs++) {
            int w = m0 + rs * 8 + r4;
            #pragma unroll
            for (int cn = 0; cn < CIN; cn++) {
                const float* xb = x + ((b * CIN + cn) * HH + s) * WW;
                xv[rs][cn]     = (w > 0) ? xb[w - 1] : 0.f;
                xv[rs][3 + cn] = xb[w];
            }
        }
        float acc[2][4];
        #pragma unroll
        for (int n8 = 0; n8 < 2; n8++)
            #pragma unroll
            for (int pq = 0; pq < 2; pq++) {
                int ncol = n0 + n8 * 8 + 2 * c4 + pq;
                float wib = WIs[6 * 128 + ncol];
                float wir[6];
                #pragma unroll
                for (int rr = 0; rr < 6; rr++) wir[rr] = WIs[rr * 128 + ncol];
                #pragma unroll
                for (int rs = 0; rs < 2; rs++) {
                    float v = wib;
                    #pragma unroll
                    for (int rr = 0; rr < 6; rr++) v += xv[rs][rr] * wir[rr];
                    acc[n8][pq + 2 * rs] = v;
                }
            }

        // ---- GEMM: 16 k16-steps (8 left-tap rows w, 8 center-tap rows w+1) ----
        #pragma unroll 4
        for (int ks = 0; ks < 16; ks++) {
            int tap = ks >> 3;
            int kc  = (ks & 7) * 16 + 4 * c4;
            unsigned long long av0 = *(const unsigned long long*)(Ac + (m0 + r4 + tap) * ASTE + kc);
            unsigned long long av1 = *(const unsigned long long*)(Ac + (m0 + r4 + tap + 8) * ASTE + kc);
            unsigned a0 = (unsigned)av0, a2 = (unsigned)(av0 >> 32);
            unsigned a1 = (unsigned)av1, a3 = (unsigned)(av1 >> 32);
            const fp16* bb = Bsm + (n0 + r4) * BSTE + tap * 128 + kc;
            #pragma unroll
            for (int n8 = 0; n8 < 2; n8++) {
                unsigned long long bv = *(const unsigned long long*)(bb + n8 * 8 * BSTE);
                MMA16(acc[n8][0], acc[n8][1], acc[n8][2], acc[n8][3],
                      a0, a1, a2, a3, (unsigned)bv, (unsigned)(bv >> 32));
            }
        }

        // ---- epilogue: gates -> c,h (fp32); out + fp16 stage into An ----
        #pragma unroll
        for (int rs = 0; rs < 2; rs++) {
            float o  = sigm(acc[0][2 * rs]);
            float f  = sigm(acc[0][2 * rs + 1]);
            float ii = sigm(acc[1][2 * rs]);
            float gg = sigm(acc[1][2 * rs + 1]);
            float cc = f * creg[rs] + ii * gg;
            creg[rs] = cc;
            float h = o * tanhf(cc);
            int w = m0 + rs * 8 + r4;
            out[((b * HC + cig) * HH + s) * WW + w] = h;
            An[(w + 1) * ASTE + spos] = __float2half(h);
        }
        __syncthreads();   // own An slice staged

        // ---- broadcast own 32-col (64 B/row) slice to the 3 peers, b64 ----
        if (tid < 512) {
            int row = (tid >> 3) + 1;             // rows 1..64
            int i   = tid & 7;
            unsigned off = AnB + (unsigned)(row * 288 + t * 64 + i * 8);
            unsigned long long v = *(const unsigned long long*)(smc + off);
            #pragma unroll
            for (int r = 0; r < CLU; r++)
                if (r != t)
                    asm volatile("st.shared::cluster.b64 [%0], %1;"
                                 :: "r"(peer[r] + off), "l"(v) : "memory");
        }

        // single cluster barrier per step: A(s+1) complete everywhere
        asm volatile("barrier.cluster.arrive.aligned;" ::: "memory");
        asm volatile("barrier.cluster.wait.aligned;" ::: "memory");
    }
}

extern "C" void kernel_launch(void* const* d_in, const int* in_sizes, int n_in,
                              void* d_out, int out_size) {
    const float* x    = (const float*)d_in[0];
    const float* W_is = (const float*)d_in[1];
    const float* b_is = (const float*)d_in[2];
    const float* W_ss = (const float*)d_in[3];
    const float* b_ss = (const float*)d_in[4];
    const float* h0   = (const float*)d_in[5];
    const float* c0   = (const float*)d_in[6];
    float* out = (float*)d_out;

    cudaFuncSetAttribute(rowlstm_kernel,
                         cudaFuncAttributeMaxDynamicSharedMemorySize, SMEM_BYTES);
    rowlstm_kernel<<<NCTA, NTHR, SMEM_BYTES>>>(x, W_is, b_is, W_ss, b_ss, h0, c0, out);
}